// round 15
// baseline (speedup 1.0000x reference)
#include <cuda_runtime.h>

// SpanIndexEncoder: out[t,f] = sum over nodes n (n < num_nodes, start_n <= t <= end_n) of emb[n,f]
// R15: row-level difference array (LOW-contention REDG: 8192x256 targets,
// ~1.5 ops/address) -> chunk sums -> shuffle chunk-prefix scan -> streaming
// output that also RE-ZEROES the diff array (no separate zero kernel, no
// event machinery, no CAP limits).
//   T = 8192 tokens, N = 8192 max nodes, F = 256 features, CHUNK = 8.

#define T_MAX  8192
#define N_MAX  8192
#define FDIM   256
#define CHUNK  8
#define NCHUNK (T_MAX / CHUNK)   // 1024

// Scratch (allocation-free). g_diff is zero at module load; k_scatter
// REDG-accumulates into it; k_out reads it and re-zeroes it -> the zero
// invariant is restored every call, so graph replays are deterministic.
__device__ float g_diff[T_MAX * FDIM];   // row-level diff array [t][f]
__device__ float g_St[NCHUNK * FDIM];    // chunk totals [c][f]
__device__ float g_P[FDIM * NCHUNK];     // exclusive chunk prefix [f][c]

// ---------------------------------------------------------------------------
// K1: scatter. One block per node, one thread per feature.
//   diff[start][f]  += emb[n][f]
//   diff[end+1][f]  -= emb[n][f]   (skip if end+1 == T_MAX)
// Coalesced 128B REDG lines; ~1.5 ops/address -> near-zero L2-atomic
// serialization (R1-validated cheap).
// ---------------------------------------------------------------------------
__global__ void __launch_bounds__(FDIM) k_scatter(const float* __restrict__ emb,
                                                  const int*   __restrict__ starts,
                                                  const int*   __restrict__ ends,
                                                  const int*   __restrict__ num_nodes_p) {
    int n = blockIdx.x;
    if (n >= *num_nodes_p) return;
    int s = starts[n];
    int e = ends[n];
    if (s > e) return;                        // empty span contributes nothing
    int f = threadIdx.x;
    float v = emb[n * FDIM + f];
    atomicAdd(&g_diff[s * FDIM + f], v);
    int e1 = e + 1;
    if (e1 < T_MAX) atomicAdd(&g_diff[e1 * FDIM + f], -v);
}

// ---------------------------------------------------------------------------
// K2: chunk totals. Block c (grid=1024), thread f: 8 independent coalesced
// L2-resident loads, tree add, one coalesced store.
// ---------------------------------------------------------------------------
__global__ void __launch_bounds__(FDIM) k_sums() {
    int c = blockIdx.x;
    int f = threadIdx.x;
    const float* db = g_diff + c * CHUNK * FDIM + f;
    float d[CHUNK];
#pragma unroll
    for (int t = 0; t < CHUNK; t++) d[t] = db[t * FDIM];
    g_St[c * FDIM + f] = ((d[0] + d[1]) + (d[2] + d[3]))
                       + ((d[4] + d[5]) + (d[6] + d[7]));
}

// ---------------------------------------------------------------------------
// K3: parallel exclusive prefix over 1024 chunks, per feature (R14-validated).
// Block b = feature (grid=256), 1024 threads; thread j owns chunk j.
// Strided g_St load (L2-resident, hidden by 262K threads), shuffle scan,
// COALESCED g_P[b][j] store.
// ---------------------------------------------------------------------------
__global__ void __launch_bounds__(1024) k_scan() {
    int b = blockIdx.x;
    int j = threadIdx.x;
    int lane = j & 31;
    int wid  = j >> 5;

    float v = g_St[j * FDIM + b];             // strided, L2-resident

    float x = v;
#pragma unroll
    for (int d = 1; d < 32; d <<= 1) {
        float u = __shfl_up_sync(0xFFFFFFFFu, x, d);
        if (lane >= d) x += u;
    }

    __shared__ float wsum[32];
    if (lane == 31) wsum[wid] = x;
    __syncthreads();
    if (wid == 0) {
        float y = wsum[lane];
#pragma unroll
        for (int d = 1; d < 32; d <<= 1) {
            float u = __shfl_up_sync(0xFFFFFFFFu, y, d);
            if (lane >= d) y += u;
        }
        wsum[lane] = y;
    }
    __syncthreads();

    float off = (wid > 0) ? wsum[wid - 1] : 0.f;
    g_P[b * NCHUNK + j] = (x + off) - v;      // exclusive prefix, coalesced
}

// ---------------------------------------------------------------------------
// K4: streaming output. Block c (grid=1024), thread f.
// acc = P[f][c]; 8 independent coalesced diff loads (issued before the scan
// chain); inclusive 8-row scan; coalesced stores; re-zero the 8 diff rows
// (fire-and-forget stores) for the next replay. No replay, no events.
// ---------------------------------------------------------------------------
__global__ void __launch_bounds__(FDIM) k_out(float* __restrict__ out) {
    int c = blockIdx.x;
    int f = threadIdx.x;

    float acc = g_P[f * NCHUNK + c];          // 1 scalar L2 hit
    float* db = g_diff + c * CHUNK * FDIM + f;
    float* ob = out    + c * CHUNK * FDIM + f;

    float d[CHUNK];
#pragma unroll
    for (int t = 0; t < CHUNK; t++) d[t] = db[t * FDIM];  // 8 loads in flight
#pragma unroll
    for (int t = 0; t < CHUNK; t++) db[t * FDIM] = 0.f;   // re-zero for next call
#pragma unroll
    for (int t = 0; t < CHUNK; t++) {
        acc += d[t];
        ob[t * FDIM] = acc;                   // coalesced
    }
}

// ---------------------------------------------------------------------------
// Inputs (metadata order): embedding f32 [8192*256], node_span_starts i32
// [8192], node_span_ends i32 [8192], num_nodes i32 [1]. Output f32 [8192*256].
// ---------------------------------------------------------------------------
extern "C" void kernel_launch(void* const* d_in, const int* in_sizes, int n_in,
                              void* d_out, int out_size) {
    const float* emb    = (const float*)d_in[0];
    const int*   starts = (const int*)d_in[1];
    const int*   ends   = (const int*)d_in[2];
    const int*   nn     = (const int*)d_in[3];
    float*       out    = (float*)d_out;

    k_scatter<<<N_MAX, FDIM>>>(emb, starts, ends, nn);
    k_sums   <<<NCHUNK, FDIM>>>();
    k_scan   <<<FDIM, NCHUNK>>>();
    k_out    <<<NCHUNK, FDIM>>>(out);
}